// round 4
// baseline (speedup 1.0000x reference)
#include <cuda_runtime.h>
#include <cuda_bf16.h>

// EEBasis: out[n, 0, s] = exp(-|zeta[s]| * sqrt(diffs[n, center_idxs[s], 3]))
// N = 262144 rows, 64 centers (float4: dx,dy,dz,r2), 256 shells (4/center).
//
// Float4-linear input index == float4-linear output index (shells are
// center-grouped). Both 256 MB streams are single-touch:
//  - __ldcs loads (evict-first), __stcs stores (streaming)
//  - persistent grid-stride: 1184 CTAs (148 SM x 8) loop over the data in
//    one wave, 2 front-batched items per iteration (split total/2 apart,
//    both streams coalesced). MLP stays 2 (R3 showed MLP=4 overflows the
//    L1tex queue at occ 8), but the request stream never drains at wave
//    boundaries.

__global__ void __launch_bounds__(256) eebasis_kernel(
    const float4* __restrict__ diffs,       // [N*64] float4
    const float4* __restrict__ zetas4,      // [64] float4 (256 zetas)
    const int*    __restrict__ center_idxs, // [256]
    float4*       __restrict__ out,         // [N*64] float4
    int half)                                // total/2
{
    const int stride = gridDim.x * blockDim.x;

    for (int i0 = blockIdx.x * blockDim.x + threadIdx.x; i0 < half; i0 += stride) {
        int i1 = i0 + half;

        int g0 = i0 & 63, n0 = i0 >> 6;
        int g1 = i1 & 63, n1 = i1 >> 6;

        // gather table (1KB, L1-resident)
        int c0 = __ldg(&center_idxs[4 * g0]);
        int c1 = __ldg(&center_idxs[4 * g1]);

        // front-batched streaming loads (MLP = 2)
        float4 d0 = __ldcs(&diffs[n0 * 64 + c0]);
        float4 d1 = __ldcs(&diffs[n1 * 64 + c1]);

        float4 z0 = __ldg(&zetas4[g0]);   // 1KB table, L1-resident
        float4 z1 = __ldg(&zetas4[g1]);

        float r0 = sqrtf(d0.w);
        float r1 = sqrtf(d1.w);

        float4 o0, o1;
        o0.x = __expf(-fabsf(z0.x) * r0);
        o0.y = __expf(-fabsf(z0.y) * r0);
        o0.z = __expf(-fabsf(z0.z) * r0);
        o0.w = __expf(-fabsf(z0.w) * r0);

        o1.x = __expf(-fabsf(z1.x) * r1);
        o1.y = __expf(-fabsf(z1.y) * r1);
        o1.z = __expf(-fabsf(z1.z) * r1);
        o1.w = __expf(-fabsf(z1.w) * r1);

        __stcs(&out[i0], o0);
        __stcs(&out[i1], o1);
    }
}

extern "C" void kernel_launch(void* const* d_in, const int* in_sizes, int n_in,
                              void* d_out, int out_size)
{
    const float* diffs       = (const float*)d_in[0];  // [N, 64, 4] f32
    const float* zetas       = (const float*)d_in[1];  // [256] f32
    const int*   center_idxs = (const int*)  d_in[2];  // [256] i32

    int n_rows = in_sizes[0] / (64 * 4);
    int total  = n_rows * 64;
    int half   = total / 2;   // N is a power of two; total even

    int threads = 256;
    int blocks  = 148 * 8;    // one full wave on GB300 (148 SMs active)

    eebasis_kernel<<<blocks, threads>>>(
        (const float4*)diffs,
        (const float4*)zetas,
        center_idxs,
        (float4*)d_out,
        half);
}

// round 5
// speedup vs baseline: 1.1474x; 1.1474x over previous
#include <cuda_runtime.h>
#include <cuda_bf16.h>

// EEBasis: out[n, 0, s] = exp(-|zeta[s]| * sqrt(diffs[n, center_idxs[s], 3]))
// N = 262144 rows, 64 centers (float4: dx,dy,dz,r2), 256 shells (4/center).
//
// Float4-linear input index == float4-linear output index (shells are
// center-grouped). Both 256 MB streams are single-touch:
//  - __ldcs loads (evict-first), __stcs stores (streaming)
//  - 2 ADJACENT items per thread (i0 = 2*tid, i1 = i0+1): the warp's two
//    LDG.128s cover the same 8 cache lines (load1 is an L1/MSHR merge),
//    halving L2 read requests vs the split-half scheme at identical DRAM
//    bytes. Stores fully dirty each 32B sector. MLP_p1 = 2 (R3 showed 4
//    distant streams overflow the L1tex queue at occ 8; R4 showed
//    persistent loops serialize the request stream).

__global__ void __launch_bounds__(256) eebasis_kernel(
    const float4* __restrict__ diffs,       // [N*64] float4
    const float4* __restrict__ zetas4,      // [64] float4 (256 zetas)
    const int*    __restrict__ center_idxs, // [256]
    float4*       __restrict__ out,         // [N*64] float4
    int half)                                // total/2
{
    int t = blockIdx.x * blockDim.x + threadIdx.x;
    if (t >= half) return;

    int i0 = 2 * t;
    int i1 = i0 + 1;

    int g0 = i0 & 63, n0 = i0 >> 6;
    int g1 = i1 & 63;              // = g0 + 1 (g0 is even), same row n0

    // gather table (1KB, L1-resident)
    int c0 = __ldg(&center_idxs[4 * g0]);
    int c1 = __ldg(&center_idxs[4 * g1]);

    // adjacent streaming loads: same 32B sector per thread, same lines per warp
    float4 d0 = __ldcs(&diffs[n0 * 64 + c0]);
    float4 d1 = __ldcs(&diffs[n0 * 64 + c1]);

    float4 z0 = __ldg(&zetas4[g0]);   // 1KB table, L1-resident
    float4 z1 = __ldg(&zetas4[g1]);

    float r0 = sqrtf(d0.w);
    float r1 = sqrtf(d1.w);

    float4 o0, o1;
    o0.x = __expf(-fabsf(z0.x) * r0);
    o0.y = __expf(-fabsf(z0.y) * r0);
    o0.z = __expf(-fabsf(z0.z) * r0);
    o0.w = __expf(-fabsf(z0.w) * r0);

    o1.x = __expf(-fabsf(z1.x) * r1);
    o1.y = __expf(-fabsf(z1.y) * r1);
    o1.z = __expf(-fabsf(z1.z) * r1);
    o1.w = __expf(-fabsf(z1.w) * r1);

    __stcs(&out[i0], o0);
    __stcs(&out[i1], o1);
}

extern "C" void kernel_launch(void* const* d_in, const int* in_sizes, int n_in,
                              void* d_out, int out_size)
{
    const float* diffs       = (const float*)d_in[0];  // [N, 64, 4] f32
    const float* zetas       = (const float*)d_in[1];  // [256] f32
    const int*   center_idxs = (const int*)  d_in[2];  // [256] i32

    int n_rows = in_sizes[0] / (64 * 4);
    int total  = n_rows * 64;
    int half   = total / 2;   // N is a power of two; total even

    int threads = 256;
    int blocks  = (half + threads - 1) / threads;

    eebasis_kernel<<<blocks, threads>>>(
        (const float4*)diffs,
        (const float4*)zetas,
        center_idxs,
        (float4*)d_out,
        half);
}